// round 13
// baseline (speedup 1.0000x reference)
#include <cuda_runtime.h>
#include <cuda_bf16.h>
#include <math.h>

// Problem dims
#define BB 128
#define TT 128
#define VV 1024
#define EE 512
#define HH 1024
#define GG 4096   // 4*H

// d_out layout (floats): decoder_outputs [B,T,H], hf [B,H], cf [B,H], symbols [B,T]
#define OUT_DEC 0
#define OUT_HF  (BB*TT*HH)
#define OUT_CF  (OUT_HF + BB*HH)
#define OUT_SYM (OUT_CF + BB*HH)

#define NCTA 128
#define NTHR 768
#define NCONS 512

// ---------------- scratch (static device memory) ----------------
__device__ float g_dec_table[VV * GG];      // emb @ dec_W_ih^T + dec_b
__device__ float g_pregates_enc[TT * GG];   // row-127 enc input pregates
__device__ float g_he[2][HH];
__device__ float g_ce[HH];
__device__ float g_hd[2][BB * HH];          // decoder h, [b][k], double buffered
__device__ float g_cd[BB * HH];             // decoder c, [b][j]
__device__ unsigned long long g_amax[2][BB];
__device__ int   g_idx64;
__device__ unsigned g_bar_count = 0;
__device__ unsigned g_bar_gen = 0;
__device__ unsigned g_gbar_cnt[4] = {0, 0, 0, 0};
__device__ unsigned g_gbar_gen[4] = {0, 0, 0, 0};

// ---------------- helpers ----------------
__device__ __forceinline__ int read_idx(const void* p, int i) {
    if (g_idx64) return (int)((const long long*)p)[i];
    return ((const int*)p)[i];
}
__device__ __forceinline__ float sigf(float x) { return 1.0f / (1.0f + expf(-x)); }

__device__ __forceinline__ void ffma2(unsigned long long& d, unsigned long long a, unsigned long long b) {
    asm("fma.rn.f32x2 %0, %1, %2, %0;" : "+l"(d) : "l"(a), "l"(b));
}
__device__ __forceinline__ unsigned long long dupf(float x) {
    unsigned long long r; unsigned u = __float_as_uint(x);
    asm("mov.b64 %0, {%1, %1};" : "=l"(r) : "r"(u));
    return r;
}
__device__ __forceinline__ float lo2(unsigned long long p) { return __uint_as_float((unsigned)p); }
__device__ __forceinline__ float hi2(unsigned long long p) { return __uint_as_float((unsigned)(p >> 32)); }
__device__ __forceinline__ unsigned monof(float v) {
    unsigned b = __float_as_uint(v);
    return b ^ ((b & 0x80000000u) ? 0xFFFFFFFFu : 0x80000000u);
}
__device__ __forceinline__ void sfma(float& d, float a, float b) {
    asm("fma.rn.f32 %0, %1, %2, %0;" : "+f"(d) : "f"(a), "f"(b));
}

// global grid barrier (all 128 CTAs resident: 1 per SM)
__device__ __forceinline__ void grid_bar() {
    __syncthreads();
    if (threadIdx.x == 0) {
        unsigned gen;
        asm volatile("ld.acquire.gpu.u32 %0, [%1];" : "=r"(gen) : "l"(&g_bar_gen));
        unsigned old;
        asm volatile("atom.add.release.gpu.u32 %0, [%1], 1;" : "=r"(old) : "l"(&g_bar_count));
        if (old == NCTA - 1) {
            g_bar_count = 0;
            asm volatile("st.release.gpu.u32 [%0], %1;" :: "l"(&g_bar_gen), "r"(gen + 1));
        } else {
            unsigned cur;
            do {
                asm volatile("ld.acquire.gpu.u32 %0, [%1];" : "=r"(cur) : "l"(&g_bar_gen));
            } while (cur == gen);
        }
    }
    __syncthreads();
}

// group barrier: 32 CTAs of one b-group (groups are independent in the decoder)
__device__ __forceinline__ void group_bar(int g) {
    __syncthreads();
    if (threadIdx.x == 0) {
        unsigned gen;
        asm volatile("ld.acquire.gpu.u32 %0, [%1];" : "=r"(gen) : "l"(&g_gbar_gen[g]));
        unsigned old;
        asm volatile("atom.add.release.gpu.u32 %0, [%1], 1;" : "=r"(old) : "l"(&g_gbar_cnt[g]));
        if (old == 31) {
            g_gbar_cnt[g] = 0;
            asm volatile("st.release.gpu.u32 [%0], %1;" :: "l"(&g_gbar_gen[g]), "r"(gen + 1));
        } else {
            unsigned cur;
            do {
                asm volatile("ld.acquire.gpu.u32 %0, [%1];" : "=r"(cur) : "l"(&g_gbar_gen[g]));
            } while (cur == gen);
        }
    }
    __syncthreads();
}

// Detect input index dtype
__global__ void detect_kernel(const void* p) {
    if (threadIdx.x == 0) {
        const unsigned long long* q = (const unsigned long long*)p;
        int ok = 1;
        for (int i = 0; i < 8; i++) if (q[i] > 1023ull) ok = 0;
        g_idx64 = ok;
    }
}

// ---------------- table GEMM (one-time) — unchanged (bit-exact lineage) ----------------
__device__ __forceinline__ void table_gemm_body(
    const float* __restrict__ A, const float* __restrict__ W,
    const float* __restrict__ bias, float* __restrict__ C,
    int K, const void* map, int map_off)
{
    __shared__ __align__(16) float Ash[16][68];
    __shared__ __align__(16) float Bsh[16][68];
    int tid = threadIdx.x;
    int tm = tid & 15, tn = tid >> 4;
    int n0 = blockIdx.x * 64, m0 = blockIdx.y * 64;

    int r  = tid >> 2;
    int kf = (tid & 3) << 2;
    int am = m0 + r;
    int arow = am;
    if (map) arow = read_idx(map, map_off + am);
    const float* Aptr = A + (size_t)arow * K;
    const float* Wptr = W + (size_t)(n0 + r) * K;

    unsigned long long accp[4][2];
#pragma unroll
    for (int i = 0; i < 4; i++) { accp[i][0] = 0ull; accp[i][1] = 0ull; }

    for (int k0 = 0; k0 < K; k0 += 16) {
        float4 av = *(const float4*)(Aptr + k0 + kf);
        float4 bv = *(const float4*)(Wptr + k0 + kf);
        __syncthreads();
        Ash[kf+0][r] = av.x; Ash[kf+1][r] = av.y; Ash[kf+2][r] = av.z; Ash[kf+3][r] = av.w;
        Bsh[kf+0][r] = bv.x; Bsh[kf+1][r] = bv.y; Bsh[kf+2][r] = bv.z; Bsh[kf+3][r] = bv.w;
        __syncthreads();
#pragma unroll
        for (int k = 0; k < 16; k++) {
            float4 a4 = *(const float4*)&Ash[k][tm * 4];
            ulonglong2 b01 = *(const ulonglong2*)&Bsh[k][tn * 4];
            unsigned long long a0 = dupf(a4.x), a1 = dupf(a4.y), a2 = dupf(a4.z), a3 = dupf(a4.w);
            ffma2(accp[0][0], b01.x, a0); ffma2(accp[0][1], b01.y, a0);
            ffma2(accp[1][0], b01.x, a1); ffma2(accp[1][1], b01.y, a1);
            ffma2(accp[2][0], b01.x, a2); ffma2(accp[2][1], b01.y, a2);
            ffma2(accp[3][0], b01.x, a3); ffma2(accp[3][1], b01.y, a3);
        }
    }
#pragma unroll
    for (int i = 0; i < 4; i++) {
        int m = m0 + tm * 4 + i;
#pragma unroll
        for (int p = 0; p < 2; p++) {
            int n = n0 + tn * 4 + p * 2;
            C[(size_t)m * GG + n]     = lo2(accp[i][p]) + bias[n];
            C[(size_t)m * GG + n + 1] = hi2(accp[i][p]) + bias[n + 1];
        }
    }
}

__global__ __launch_bounds__(256) void table_dec_kernel(
    const float* __restrict__ emb, const float* __restrict__ W, const float* __restrict__ bias)
{
    table_gemm_body(emb, W, bias, g_dec_table, EE, nullptr, 0);
}
__global__ __launch_bounds__(256) void table_pre_kernel(
    const float* __restrict__ emb, const float* __restrict__ W, const float* __restrict__ bias,
    const void* __restrict__ inputs)
{
    table_gemm_body(emb, W, bias, g_pregates_enc, EE, inputs, 127 * TT);
}

// ---------------- persistent main kernel (16 consumer + 8 producer warps, SCALAR FFMA) ----------------
// smem layout (floats):
//   wbuf: double-buffered w tiles, 2 x 128x33 at offsets 0 / 4224  (gates)
//         fc reuses as 2 x 32x33 at offsets 0 / 1056
//   gsh:  gate pre-activation staging [128][34] aliases wbuf (dead at staging)
//   hbuf: double-buffered h^T chunks, 2 x 32x36 at offsets 8448 / 9600
#define WBUF_OFF  0
#define WBUF_STRIDE 4224
#define WBUF_STRIDE_FC 1056
#define HBUF_OFF  8448
#define HBUF_STRIDE 1152

struct MainSmem {
    __align__(16) float buf[10752];   // 43 KB
    int ssym[32];
};

__global__ __launch_bounds__(NTHR, 1) void main_kernel(
    const void* __restrict__ inputs,
    const float* __restrict__ eWhh,
    const float* __restrict__ dWhh,
    const float* __restrict__ fcW,
    const float* __restrict__ fcb,
    float* __restrict__ out)
{
    __shared__ MainSmem smem;
    const int cta = blockIdx.x;
    const int tid = threadIdx.x;
    const bool cons = tid < NCONS;       // warps 0-15 consumers, 16-23 producers
    const int ptid = tid - NCONS;        // producer-local id 0..255
    const int grp4 = cta >> 5;           // b-group id (0..3)

    // ---- phase 0: zero encoder state ----
    if (cta == 0) {
        for (int i = tid; i < HH; i += NTHR) { g_he[0][i] = 0.0f; g_ce[i] = 0.0f; }
    }
    grid_bar();

    // ---- encoder: batch row 127 only (first 8 warps compute; all hit grid_bar) ----
    {
        const int wid = tid >> 5, lane = tid & 31;
        const int j = cta * 8 + wid;
        const float* w = eWhh + (size_t)j * HH;
        for (int t = 0; t < TT; t++) {
            if (wid < 8) {
                const float* hin = g_he[t & 1];
                float a0 = 0.f, a1 = 0.f, a2 = 0.f, a3 = 0.f;
#pragma unroll 4
                for (int k = lane; k < HH; k += 32) {
                    float hv = hin[k];
                    a0 += hv * w[k];
                    a1 += hv * w[1024 * 1024 + k];
                    a2 += hv * w[2 * 1024 * 1024 + k];
                    a3 += hv * w[3 * 1024 * 1024 + k];
                }
#pragma unroll
                for (int o = 16; o; o >>= 1) {
                    a0 += __shfl_xor_sync(0xffffffffu, a0, o);
                    a1 += __shfl_xor_sync(0xffffffffu, a1, o);
                    a2 += __shfl_xor_sync(0xffffffffu, a2, o);
                    a3 += __shfl_xor_sync(0xffffffffu, a3, o);
                }
                if (lane == 0) {
                    const float* pg = g_pregates_enc + (size_t)t * GG;
                    float gi = a0 + pg[j];
                    float gf = a1 + pg[HH + j];
                    float gg = a2 + pg[2 * HH + j];
                    float go = a3 + pg[3 * HH + j];
                    float i_ = sigf(gi), f_ = sigf(gf), c_ = tanhf(gg), o_ = sigf(go);
                    float c = f_ * g_ce[j] + i_ * c_;
                    g_ce[j] = c;
                    g_he[(t + 1) & 1][j] = o_ * tanhf(c);
                }
            }
            grid_bar();
        }
    }

    // ---- decoder init ----
    if (tid < NCONS) {
        int base = cta * 1024 + tid * 2;
#pragma unroll
        for (int q = 0; q < 2; q++) {
            int k = tid * 2 + q;
            g_hd[0][base + q] = (cta == 127) ? g_he[0][k] : 0.0f;
            g_cd[base + q]    = (cta == 127) ? g_ce[k]    : 0.0f;
        }
    }
    grid_bar();

    // ---- decoder: 128 steps ----
    const int j0 = (cta & 31) * 32;          // gates j-tile / fc n-tile
    const int b0 = (cta >> 5) * 32;          // b-tile

    // consumer gates mapping: thread owns 1 col x 8 b (octet bo)
    const int col = tid & 127;               // 0..127 (consumer)
    const int bo  = (tid >> 7) & 3;          // 0..3 warp-uniform (consumer)
    // consumer fc mapping: n = lane, 2 b's
    const int fn = tid & 31;
    const int bg = (tid >> 5) & 15;          // 0..15 warp-uniform (consumer)
    // producer h mapping
    const int phb = ptid >> 3;               // 0..31
    const int phk = (ptid & 7) << 2;

    float* buf = smem.buf;
    float* gsh = smem.buf;                   // staging aliases w buffers

    for (int t = 0; t < TT; t++) {
        // ===== gates phase: pregate = dec_table[sym] + h @ W_hh^T =====
        {
            const float* hin = g_hd[t & 1];
            float* hout = g_hd[(t + 1) & 1];

            if (tid < 32) {
                int b = b0 + tid;
                int s;
                if (t == 0) {
                    s = read_idx(inputs, b * TT);
                } else {
                    unsigned long long key = g_amax[(t - 1) & 1][b];
                    s = (int)(~(unsigned)key & 1023u);
                    if ((cta & 31) == 0) out[OUT_SYM + b * TT + (t - 1)] = (float)s;
                }
                smem.ssym[tid] = s;
            }
            if ((cta & 31) == 0 && tid < 32) g_amax[t & 1][b0 + tid] = 0ull;

            // prologue: producers fill buffer 0 (chunk 0)
            if (!cons) {
#pragma unroll
                for (int i = 0; i < 4; i++) {
                    int q = i * 256 + ptid;
                    int c = q >> 3; int ks = (q & 7) << 2;
                    int g = c >> 5, jj = c & 31;
                    float4 v = *(const float4*)(dWhh + ((size_t)(g * HH + j0 + jj)) * HH + ks);
                    float* p = buf + WBUF_OFF + c * 33 + ks;
                    p[0] = v.x; p[1] = v.y; p[2] = v.z; p[3] = v.w;
                }
                {
                    float4 v = *(const float4*)(hin + (size_t)(b0 + phb) * HH + phk);
                    float* p = buf + HBUF_OFF + phk * 36 + phb;
                    p[0] = v.x; p[36] = v.y; p[72] = v.z; p[108] = v.w;
                }
            }
            __syncthreads();

            float acc[8] = {0.f, 0.f, 0.f, 0.f, 0.f, 0.f, 0.f, 0.f};

            for (int ch = 0; ch < 32; ch++) {
                if (cons) {
                    const float* wp = buf + WBUF_OFF + (ch & 1) * WBUF_STRIDE + col * 33;
                    const float* hb = buf + HBUF_OFF + (ch & 1) * HBUF_STRIDE + bo * 8;
#pragma unroll
                    for (int k = 0; k < 32; k++) {
                        float4 h0 = *(const float4*)(hb + k * 36);       // b 0..3 (broadcast)
                        float4 h1 = *(const float4*)(hb + k * 36 + 4);   // b 4..7 (broadcast)
                        float w = wp[k];
                        sfma(acc[0], h0.x, w); sfma(acc[1], h0.y, w);
                        sfma(acc[2], h0.z, w); sfma(acc[3], h0.w, w);
                        sfma(acc[4], h1.x, w); sfma(acc[5], h1.y, w);
                        sfma(acc[6], h1.z, w); sfma(acc[7], h1.w, w);
                    }
                } else if (ch < 31) {
                    int k0 = (ch + 1) * 32;
                    float* wt = buf + WBUF_OFF + ((ch + 1) & 1) * WBUF_STRIDE;
                    float* hbw = buf + HBUF_OFF + ((ch + 1) & 1) * HBUF_STRIDE;
#pragma unroll
                    for (int i = 0; i < 4; i++) {
                        int q = i * 256 + ptid;
                        int c = q >> 3; int ks = (q & 7) << 2;
                        int g = c >> 5, jj = c & 31;
                        float4 v = *(const float4*)(dWhh + ((size_t)(g * HH + j0 + jj)) * HH + k0 + ks);
                        float* p = wt + c * 33 + ks;
                        p[0] = v.x; p[1] = v.y; p[2] = v.z; p[3] = v.w;
                    }
                    {
                        float4 v = *(const float4*)(hin + (size_t)(b0 + phb) * HH + k0 + phk);
                        float* p = hbw + phk * 36 + phb;
                        p[0] = v.x; p[36] = v.y; p[72] = v.z; p[108] = v.w;
                    }
                }
                __syncthreads();
            }

            // stage pre-activations [col][b] (w buffers dead); same memory layout as before
            if (cons) {
                float* gp = gsh + col * 34 + bo * 8;
#pragma unroll
                for (int i = 0; i < 8; i++) gp[i] = acc[i];
            }
            __syncthreads();

            // LSTM epilogue: consumer threads, each 2 b's
            if (tid < NCONS) {
                int jj = tid & 31;
                int grp = tid >> 5;               // 0..15
                int jg = j0 + jj;
#pragma unroll
                for (int i = 0; i < 2; i++) {
                    int b = grp * 2 + i;
                    int s = smem.ssym[b];
                    const float* tb = g_dec_table + (size_t)s * GG + jg;
                    float gi = gsh[(0 * 32 + jj) * 34 + b] + tb[0];
                    float gf = gsh[(1 * 32 + jj) * 34 + b] + tb[HH];
                    float gg = gsh[(2 * 32 + jj) * 34 + b] + tb[2 * HH];
                    float go = gsh[(3 * 32 + jj) * 34 + b] + tb[3 * HH];
                    float i_ = sigf(gi), f_ = sigf(gf), c_ = tanhf(gg), o_ = sigf(go);
                    int off = (b0 + b) * HH + jg;
                    float c = f_ * g_cd[off] + i_ * c_;
                    g_cd[off] = c;
                    hout[off] = o_ * tanhf(c);
                }
            }
        }
        group_bar(grp4);

        // ===== fc phase: logits = h @ fc_W^T + fc_b; write + argmax =====
        {
            const float* h = g_hd[(t + 1) & 1];

            // prologue: producers fill buffer 0
            if (!cons) {
                {
                    int n = ptid >> 3; int ks = (ptid & 7) << 2;
                    float4 v = *(const float4*)(fcW + (size_t)(j0 + n) * HH + ks);
                    float* p = buf + WBUF_OFF + n * 33 + ks;
                    p[0] = v.x; p[1] = v.y; p[2] = v.z; p[3] = v.w;
                }
                {
                    float4 v = *(const float4*)(h + (size_t)(b0 + phb) * HH + phk);
                    float* p = buf + HBUF_OFF + phk * 36 + phb;
                    p[0] = v.x; p[36] = v.y; p[72] = v.z; p[108] = v.w;
                }
            }
            __syncthreads();

            float a0 = 0.f, a1 = 0.f;

            for (int ch = 0; ch < 32; ch++) {
                if (cons) {
                    const float* wp = buf + WBUF_OFF + (ch & 1) * WBUF_STRIDE_FC + fn * 33;
                    const float* hb = buf + HBUF_OFF + (ch & 1) * HBUF_STRIDE + bg * 2;
#pragma unroll
                    for (int k = 0; k < 32; k++) {
                        float2 hp = *(const float2*)(hb + k * 36);   // broadcast
                        float w = wp[k];
                        sfma(a0, hp.x, w);
                        sfma(a1, hp.y, w);
                    }
                } else if (ch < 31) {
                    int k0 = (ch + 1) * 32;
                    float* wt = buf + WBUF_OFF + ((ch + 1) & 1) * WBUF_STRIDE_FC;
                    float* hbw = buf + HBUF_OFF + ((ch + 1) & 1) * HBUF_STRIDE;
                    {
                        int n = ptid >> 3; int ks = (ptid & 7) << 2;
                        float4 v = *(const float4*)(fcW + (size_t)(j0 + n) * HH + k0 + ks);
                        float* p = wt + n * 33 + ks;
                        p[0] = v.x; p[1] = v.y; p[2] = v.z; p[3] = v.w;
                    }
                    {
                        float4 v = *(const float4*)(h + (size_t)(b0 + phb) * HH + k0 + phk);
                        float* p = hbw + phk * 36 + phb;
                        p[0] = v.x; p[36] = v.y; p[72] = v.z; p[108] = v.w;
                    }
                }
                __syncthreads();
            }

            if (cons) {
                int n = j0 + fn;
                float bias = fcb[n];
                float v[2] = { a0 + bias, a1 + bias };
#pragma unroll
                for (int i = 0; i < 2; i++) {
                    int b = b0 + bg * 2 + i;
                    out[OUT_DEC + (size_t)b * TT * HH + (size_t)t * HH + n] = v[i];
                }
#pragma unroll
                for (int i = 0; i < 2; i++) {
                    unsigned long long key =
                        ((unsigned long long)monof(v[i]) << 32) | (unsigned)(~(unsigned)n);
#pragma unroll
                    for (int off = 16; off; off >>= 1) {
                        unsigned long long o = __shfl_xor_sync(0xffffffffu, key, off);
                        if (o > key) key = o;
                    }
                    if (fn == 0) atomicMax(&g_amax[t & 1][b0 + bg * 2 + i], key);
                }
            }
        }
        group_bar(grp4);
    }

    // ---- final: symbols for t=127, hf/cf (group-local; groups independent) ----
    if ((cta & 31) == 0 && tid < 32) {
        int b = b0 + tid;
        unsigned long long key = g_amax[1][b];
        out[OUT_SYM + b * TT + 127] = (float)(~(unsigned)key & 1023u);
    }
    if (tid < NCONS) {
        int base = cta * 1024 + tid * 2;
#pragma unroll
        for (int q = 0; q < 2; q++) {
            out[OUT_HF + base + q] = g_hd[0][base + q];
            out[OUT_CF + base + q] = g_cd[base + q];
        }
    }
}

// ---------------- launcher ----------------
extern "C" void kernel_launch(void* const* d_in, const int* in_sizes, int n_in,
                              void* d_out, int out_size) {
    const void*  inputs = d_in[0];
    const float* emb    = (const float*)d_in[1];
    const float* eWih   = (const float*)d_in[2];
    const float* eWhh   = (const float*)d_in[3];
    const float* eb     = (const float*)d_in[4];
    const float* dWih   = (const float*)d_in[5];
    const float* dWhh   = (const float*)d_in[6];
    const float* db     = (const float*)d_in[7];
    const float* fcW    = (const float*)d_in[8];
    const float* fcb    = (const float*)d_in[9];
    float* out = (float*)d_out;

    detect_kernel<<<1, 32>>>(inputs);
    table_dec_kernel<<<dim3(64, 16), 256>>>(emb, dWih, db);
    table_pre_kernel<<<dim3(64, 2), 256>>>(emb, eWih, eb, inputs);
    main_kernel<<<NCTA, NTHR>>>(inputs, eWhh, dWhh, fcW, fcb, out);
}

// round 16
// speedup vs baseline: 1.2773x; 1.2773x over previous
#include <cuda_runtime.h>
#include <cuda_bf16.h>
#include <math.h>

// Problem dims
#define BB 128
#define TT 128
#define VV 1024
#define EE 512
#define HH 1024
#define GG 4096   // 4*H

// d_out layout (floats): decoder_outputs [B,T,H], hf [B,H], cf [B,H], symbols [B,T]
#define OUT_DEC 0
#define OUT_HF  (BB*TT*HH)
#define OUT_CF  (OUT_HF + BB*HH)
#define OUT_SYM (OUT_CF + BB*HH)

#define NCTA 128

// ---------------- scratch (static device memory) ----------------
__device__ float g_dec_table[VV * GG];      // emb @ dec_W_ih^T + dec_b
__device__ float g_pregates_enc[TT * GG];   // row-127 enc input pregates
__device__ float g_he[2][HH];
__device__ float g_ce[HH];
__device__ float g_hd[2][BB * HH];          // decoder h, [b][k], double buffered
__device__ float g_cd[BB * HH];             // decoder c, [b][j]
__device__ unsigned long long g_amax[2][BB];
__device__ int   g_idx64;
__device__ unsigned g_bar_count = 0;
__device__ unsigned g_bar_gen = 0;

// ---------------- helpers ----------------
__device__ __forceinline__ int read_idx(const void* p, int i) {
    if (g_idx64) return (int)((const long long*)p)[i];
    return ((const int*)p)[i];
}
__device__ __forceinline__ float sigf(float x) { return 1.0f / (1.0f + expf(-x)); }

__device__ __forceinline__ void ffma2(unsigned long long& d, unsigned long long a, unsigned long long b) {
    asm("fma.rn.f32x2 %0, %1, %2, %0;" : "+l"(d) : "l"(a), "l"(b));
}
__device__ __forceinline__ unsigned long long dupf(float x) {
    unsigned long long r; unsigned u = __float_as_uint(x);
    asm("mov.b64 %0, {%1, %1};" : "=l"(r) : "r"(u));
    return r;
}
__device__ __forceinline__ float lo2(unsigned long long p) { return __uint_as_float((unsigned)p); }
__device__ __forceinline__ float hi2(unsigned long long p) { return __uint_as_float((unsigned)(p >> 32)); }
__device__ __forceinline__ unsigned monof(float v) {
    unsigned b = __float_as_uint(v);
    return b ^ ((b & 0x80000000u) ? 0xFFFFFFFFu : 0x80000000u);
}
__device__ __forceinline__ void sfma(float& d, float a, float b) {
    asm("fma.rn.f32 %0, %1, %2, %0;" : "+f"(d) : "f"(a), "f"(b));
}

// grid barrier: release/acquire gpu scope (all 128 CTAs resident: 1 per SM)
__device__ __forceinline__ void grid_bar() {
    __syncthreads();
    if (threadIdx.x == 0) {
        unsigned gen;
        asm volatile("ld.acquire.gpu.u32 %0, [%1];" : "=r"(gen) : "l"(&g_bar_gen));
        unsigned old;
        asm volatile("atom.add.release.gpu.u32 %0, [%1], 1;" : "=r"(old) : "l"(&g_bar_count));
        if (old == NCTA - 1) {
            g_bar_count = 0;
            asm volatile("st.release.gpu.u32 [%0], %1;" :: "l"(&g_bar_gen), "r"(gen + 1));
        } else {
            unsigned cur;
            do {
                asm volatile("ld.acquire.gpu.u32 %0, [%1];" : "=r"(cur) : "l"(&g_bar_gen));
            } while (cur == gen);
        }
    }
    __syncthreads();
}

// Detect input index dtype
__global__ void detect_kernel(const void* p) {
    if (threadIdx.x == 0) {
        const unsigned long long* q = (const unsigned long long*)p;
        int ok = 1;
        for (int i = 0; i < 8; i++) if (q[i] > 1023ull) ok = 0;
        g_idx64 = ok;
    }
}

// ---------------- table GEMM (one-time) — unchanged (bit-exact lineage) ----------------
__device__ __forceinline__ void table_gemm_body(
    const float* __restrict__ A, const float* __restrict__ W,
    const float* __restrict__ bias, float* __restrict__ C,
    int K, const void* map, int map_off)
{
    __shared__ __align__(16) float Ash[16][68];
    __shared__ __align__(16) float Bsh[16][68];
    int tid = threadIdx.x;
    int tm = tid & 15, tn = tid >> 4;
    int n0 = blockIdx.x * 64, m0 = blockIdx.y * 64;

    int r  = tid >> 2;
    int kf = (tid & 3) << 2;
    int am = m0 + r;
    int arow = am;
    if (map) arow = read_idx(map, map_off + am);
    const float* Aptr = A + (size_t)arow * K;
    const float* Wptr = W + (size_t)(n0 + r) * K;

    unsigned long long accp[4][2];
#pragma unroll
    for (int i = 0; i < 4; i++) { accp[i][0] = 0ull; accp[i][1] = 0ull; }

    for (int k0 = 0; k0 < K; k0 += 16) {
        float4 av = *(const float4*)(Aptr + k0 + kf);
        float4 bv = *(const float4*)(Wptr + k0 + kf);
        __syncthreads();
        Ash[kf+0][r] = av.x; Ash[kf+1][r] = av.y; Ash[kf+2][r] = av.z; Ash[kf+3][r] = av.w;
        Bsh[kf+0][r] = bv.x; Bsh[kf+1][r] = bv.y; Bsh[kf+2][r] = bv.z; Bsh[kf+3][r] = bv.w;
        __syncthreads();
#pragma unroll
        for (int k = 0; k < 16; k++) {
            float4 a4 = *(const float4*)&Ash[k][tm * 4];
            ulonglong2 b01 = *(const ulonglong2*)&Bsh[k][tn * 4];
            unsigned long long a0 = dupf(a4.x), a1 = dupf(a4.y), a2 = dupf(a4.z), a3 = dupf(a4.w);
            ffma2(accp[0][0], b01.x, a0); ffma2(accp[0][1], b01.y, a0);
            ffma2(accp[1][0], b01.x, a1); ffma2(accp[1][1], b01.y, a1);
            ffma2(accp[2][0], b01.x, a2); ffma2(accp[2][1], b01.y, a2);
            ffma2(accp[3][0], b01.x, a3); ffma2(accp[3][1], b01.y, a3);
        }
    }
#pragma unroll
    for (int i = 0; i < 4; i++) {
        int m = m0 + tm * 4 + i;
#pragma unroll
        for (int p = 0; p < 2; p++) {
            int n = n0 + tn * 4 + p * 2;
            C[(size_t)m * GG + n]     = lo2(accp[i][p]) + bias[n];
            C[(size_t)m * GG + n + 1] = hi2(accp[i][p]) + bias[n + 1];
        }
    }
}

__global__ __launch_bounds__(256) void table_dec_kernel(
    const float* __restrict__ emb, const float* __restrict__ W, const float* __restrict__ bias)
{
    table_gemm_body(emb, W, bias, g_dec_table, EE, nullptr, 0);
}
__global__ __launch_bounds__(256) void table_pre_kernel(
    const float* __restrict__ emb, const float* __restrict__ W, const float* __restrict__ bias,
    const void* __restrict__ inputs)
{
    table_gemm_body(emb, W, bias, g_pregates_enc, EE, inputs, 127 * TT);
}

// ---------------- persistent main kernel (R3 structure, scalar-FFMA inner loops) ----------------
struct MainSmem {
    __align__(16) float wsh[128][33];   // gates w[col][k]; fc reuses rows [n][k]
    __align__(16) float hsh[32][36];    // h[k][b] transposed chunk
    __align__(16) float gsh[128][34];   // gate pre-activation staging [col][b]
    int ssym[32];
};

__global__ __launch_bounds__(256, 1) void main_kernel(
    const void* __restrict__ inputs,
    const float* __restrict__ eWhh,
    const float* __restrict__ dWhh,
    const float* __restrict__ fcW,
    const float* __restrict__ fcb,
    float* __restrict__ out)
{
    __shared__ MainSmem smem;
    const int cta = blockIdx.x;
    const int tid = threadIdx.x;

    // ---- phase 0: zero encoder state ----
    if (cta == 0) {
        for (int i = tid; i < HH; i += 256) { g_he[0][i] = 0.0f; g_ce[i] = 0.0f; }
    }
    grid_bar();

    // ---- encoder: batch row 127 only, 128 steps ----
    {
        const int wid = tid >> 5, lane = tid & 31;
        const int j = cta * 8 + wid;
        const float* w = eWhh + (size_t)j * HH;
        for (int t = 0; t < TT; t++) {
            const float* hin = g_he[t & 1];
            float a0 = 0.f, a1 = 0.f, a2 = 0.f, a3 = 0.f;
#pragma unroll 4
            for (int k = lane; k < HH; k += 32) {
                float hv = hin[k];
                a0 += hv * w[k];
                a1 += hv * w[1024 * 1024 + k];
                a2 += hv * w[2 * 1024 * 1024 + k];
                a3 += hv * w[3 * 1024 * 1024 + k];
            }
#pragma unroll
            for (int o = 16; o; o >>= 1) {
                a0 += __shfl_xor_sync(0xffffffffu, a0, o);
                a1 += __shfl_xor_sync(0xffffffffu, a1, o);
                a2 += __shfl_xor_sync(0xffffffffu, a2, o);
                a3 += __shfl_xor_sync(0xffffffffu, a3, o);
            }
            if (lane == 0) {
                const float* pg = g_pregates_enc + (size_t)t * GG;
                float gi = a0 + pg[j];
                float gf = a1 + pg[HH + j];
                float gg = a2 + pg[2 * HH + j];
                float go = a3 + pg[3 * HH + j];
                float i_ = sigf(gi), f_ = sigf(gf), c_ = tanhf(gg), o_ = sigf(go);
                float c = f_ * g_ce[j] + i_ * c_;
                g_ce[j] = c;
                g_he[(t + 1) & 1][j] = o_ * tanhf(c);
            }
            grid_bar();
        }
    }

    // ---- decoder init ----
    {
        int base = cta * 1024 + tid * 4;
#pragma unroll
        for (int q = 0; q < 4; q++) {
            int k = tid * 4 + q;
            g_hd[0][base + q] = (cta == 127) ? g_he[0][k] : 0.0f;
            g_cd[base + q]    = (cta == 127) ? g_ce[k]    : 0.0f;
        }
    }
    grid_bar();

    // ---- decoder: 128 steps ----
    const int j0 = (cta & 31) * 32;          // gates j-tile / fc n-tile
    const int b0 = (cta >> 5) * 32;          // b-tile

    // gates inner-thread mapping (thread = cols {cg, cg+64} x 8 b's)
    const int bo = tid >> 6;                 // 0..3 (b-octet, warp-uniform)
    const int cg = tid & 63;                 // 0..63
    // fc mapping (thread = 1 n x 4 b's)
    const int fn = tid & 31;                 // n within tile (lane)
    const int bq = tid >> 5;                 // 0..7 (b-quad, warp-uniform)

    float* gshp = &smem.gsh[0][0];
    float* wshp = &smem.wsh[0][0];
    float* hshp = &smem.hsh[0][0];

    for (int t = 0; t < TT; t++) {
        // ===== gates phase =====
        {
            const float* hin = g_hd[t & 1];
            float* hout = g_hd[(t + 1) & 1];

            // symbol preamble
            if (tid < 32) {
                int b = b0 + tid;
                int s;
                if (t == 0) {
                    s = read_idx(inputs, b * TT);
                } else {
                    unsigned long long key = g_amax[(t - 1) & 1][b];
                    s = (int)(~(unsigned)key & 1023u);
                    if ((cta & 31) == 0) out[OUT_SYM + b * TT + (t - 1)] = (float)s;
                }
                smem.ssym[tid] = s;
            }
            if (cta == 0 && tid < BB) g_amax[t & 1][tid] = 0ull;

            float accA[8] = {0.f,0.f,0.f,0.f,0.f,0.f,0.f,0.f};   // col cg
            float accB[8] = {0.f,0.f,0.f,0.f,0.f,0.f,0.f,0.f};   // col cg+64

            // prefetch regs
            float4 wreg[4];
            float4 hreg;
            const int hb = tid >> 3;                 // 0..31
            const int hk = (tid & 7) << 2;           // 0..28
            {
#pragma unroll
                for (int i = 0; i < 4; i++) {
                    int q = i * 256 + tid;
                    int c = q >> 3;
                    int ks = (q & 7) << 2;
                    int g = c >> 5, jj = c & 31;
                    wreg[i] = *(const float4*)(dWhh + ((size_t)(g * HH + j0 + jj)) * HH + ks);
                }
                hreg = *(const float4*)(hin + (size_t)(b0 + hb) * HH + hk);
            }

            const float* hbase = hshp + bo * 8;
            const float* w0p = wshp + cg * 33;
            const float* w1p = wshp + (cg + 64) * 33;

            for (int ch = 0; ch < 32; ch++) {
                __syncthreads();
#pragma unroll
                for (int i = 0; i < 4; i++) {
                    int q = i * 256 + tid;
                    int c = q >> 3;
                    int ks = (q & 7) << 2;
                    float* p = wshp + c * 33 + ks;
                    p[0] = wreg[i].x; p[1] = wreg[i].y; p[2] = wreg[i].z; p[3] = wreg[i].w;
                }
                {
                    float* p = hshp + hk * 36 + hb;
                    p[0] = hreg.x; p[36] = hreg.y; p[72] = hreg.z; p[108] = hreg.w;
                }
                if (ch < 31) {
                    int k0 = (ch + 1) * 32;
#pragma unroll
                    for (int i = 0; i < 4; i++) {
                        int q = i * 256 + tid;
                        int c = q >> 3;
                        int ks = (q & 7) << 2;
                        int g = c >> 5, jj = c & 31;
                        wreg[i] = *(const float4*)(dWhh + ((size_t)(g * HH + j0 + jj)) * HH + k0 + ks);
                    }
                    hreg = *(const float4*)(hin + (size_t)(b0 + hb) * HH + k0 + hk);
                }
                __syncthreads();
#pragma unroll
                for (int k = 0; k < 32; k++) {
                    float4 h0 = *(const float4*)(hbase + k * 36);       // b0..b3 (bcast)
                    float4 h1 = *(const float4*)(hbase + k * 36 + 4);   // b4..b7 (bcast)
                    float w0 = w0p[k];
                    float w1 = w1p[k];
                    sfma(accA[0], h0.x, w0); sfma(accA[1], h0.y, w0);
                    sfma(accA[2], h0.z, w0); sfma(accA[3], h0.w, w0);
                    sfma(accA[4], h1.x, w0); sfma(accA[5], h1.y, w0);
                    sfma(accA[6], h1.z, w0); sfma(accA[7], h1.w, w0);
                    sfma(accB[0], h0.x, w1); sfma(accB[1], h0.y, w1);
                    sfma(accB[2], h0.z, w1); sfma(accB[3], h0.w, w1);
                    sfma(accB[4], h1.x, w1); sfma(accB[5], h1.y, w1);
                    sfma(accB[6], h1.z, w1); sfma(accB[7], h1.w, w1);
                }
            }

            // stage pre-activations to gsh[col][b]
            __syncthreads();
            {
                float* pA = gshp + cg * 34 + bo * 8;
                float* pB = gshp + (cg + 64) * 34 + bo * 8;
#pragma unroll
                for (int i = 0; i < 8; i++) { pA[i] = accA[i]; pB[i] = accB[i]; }
            }
            __syncthreads();

            // LSTM epilogue: thread: jj = tid&31, 4 b's
            {
                int jj = tid & 31;
                int bl = (tid >> 5) * 4;
                int jg = j0 + jj;
#pragma unroll
                for (int i = 0; i < 4; i++) {
                    int b = bl + i;
                    int s = smem.ssym[b];
                    const float* tb = g_dec_table + (size_t)s * GG + jg;
                    float gi = gshp[(0 * 32 + jj) * 34 + b] + tb[0];
                    float gf = gshp[(1 * 32 + jj) * 34 + b] + tb[HH];
                    float gg = gshp[(2 * 32 + jj) * 34 + b] + tb[2 * HH];
                    float go = gshp[(3 * 32 + jj) * 34 + b] + tb[3 * HH];
                    float i_ = sigf(gi), f_ = sigf(gf), c_ = tanhf(gg), o_ = sigf(go);
                    int off = (b0 + b) * HH + jg;
                    float c = f_ * g_cd[off] + i_ * c_;
                    g_cd[off] = c;
                    hout[off] = o_ * tanhf(c);
                }
            }
        }
        grid_bar();

        // ===== fc phase: logits = h @ fc_W^T + fc_b; write + argmax =====
        {
            const float* h = g_hd[(t + 1) & 1];
            float af[4] = {0.f, 0.f, 0.f, 0.f};

            float4 wreg;
            float4 hreg;
            const int wn = tid >> 3;                // 0..31
            const int wk = (tid & 7) << 2;
            const int hb = tid >> 3;
            const int hk = (tid & 7) << 2;
            wreg = *(const float4*)(fcW + (size_t)(j0 + wn) * HH + wk);
            hreg = *(const float4*)(h + (size_t)(b0 + hb) * HH + hk);

            const float* hbase = hshp + bq * 4;
            const float* wp = wshp + fn * 33;

            for (int ch = 0; ch < 32; ch++) {
                __syncthreads();
                {
                    float* p = wshp + wn * 33 + wk;
                    p[0] = wreg.x; p[1] = wreg.y; p[2] = wreg.z; p[3] = wreg.w;
                    float* ph = hshp + hk * 36 + hb;
                    ph[0] = hreg.x; ph[36] = hreg.y; ph[72] = hreg.z; ph[108] = hreg.w;
                }
                if (ch < 31) {
                    int k0 = (ch + 1) * 32;
                    wreg = *(const float4*)(fcW + (size_t)(j0 + wn) * HH + k0 + wk);
                    hreg = *(const float4*)(h + (size_t)(b0 + hb) * HH + k0 + hk);
                }
                __syncthreads();
#pragma unroll
                for (int k = 0; k < 32; k++) {
                    float4 hp = *(const float4*)(hbase + k * 36);   // b quad (bcast)
                    float w = wp[k];
                    sfma(af[0], hp.x, w);
                    sfma(af[1], hp.y, w);
                    sfma(af[2], hp.z, w);
                    sfma(af[3], hp.w, w);
                }
            }

            int n = j0 + fn;
            float bias = fcb[n];
            float v[4] = { af[0] + bias, af[1] + bias, af[2] + bias, af[3] + bias };
#pragma unroll
            for (int i = 0; i < 4; i++) {
                int b = b0 + bq * 4 + i;
                out[OUT_DEC + (size_t)b * TT * HH + (size_t)t * HH + n] = v[i];
            }
#pragma unroll
            for (int i = 0; i < 4; i++) {
                unsigned long long key =
                    ((unsigned long long)monof(v[i]) << 32) | (unsigned)(~(unsigned)n);
#pragma unroll
                for (int off = 16; off; off >>= 1) {
                    unsigned long long o = __shfl_xor_sync(0xffffffffu, key, off);
                    if (o > key) key = o;
                }
                if (fn == 0) atomicMax(&g_amax[t & 1][b0 + bq * 4 + i], key);
            }
        }
        grid_bar();
    }

    // ---- final: symbols for t=127, hf/cf ----
    if ((cta & 31) == 0 && tid < 32) {
        int b = b0 + tid;
        unsigned long long key = g_amax[1][b];
        out[OUT_SYM + b * TT + 127] = (float)(~(unsigned)key & 1023u);
    }
    {
        int base = cta * 1024 + tid * 4;
#pragma unroll
        for (int q = 0; q < 4; q++) {
            out[OUT_HF + base + q] = g_hd[0][base + q];
            out[OUT_CF + base + q] = g_cd[base + q];
        }
    }
}

// ---------------- launcher ----------------
extern "C" void kernel_launch(void* const* d_in, const int* in_sizes, int n_in,
                              void* d_out, int out_size) {
    const void*  inputs = d_in[0];
    const float* emb    = (const float*)d_in[1];
    const float* eWih   = (const float*)d_in[2];
    const float* eWhh   = (const float*)d_in[3];
    const float* eb     = (const float*)d_in[4];
    const float* dWih   = (const float*)d_in[5];
    const float* dWhh   = (const float*)d_in[6];
    const float* db     = (const float*)d_in[7];
    const float* fcW    = (const float*)d_in[8];
    const float* fcb    = (const float*)d_in[9];
    float* out = (float*)d_out;

    detect_kernel<<<1, 32>>>(inputs);
    table_dec_kernel<<<dim3(64, 16), 256>>>(emb, dWih, db);
    table_pre_kernel<<<dim3(64, 2), 256>>>(emb, eWih, eb, inputs);
    main_kernel<<<NCTA, 256>>>(inputs, eWhh, dWhh, fcW, fcb, out);
}